// round 4
// baseline (speedup 1.0000x reference)
#include <cuda_runtime.h>
#include <cstdint>

// Problem constants
#define Bc  2
#define Tc  2048
#define Cc  1024
#define Hc  16
#define DHc 64

// Scratch (device globals: no allocations allowed)
__device__ float g_q[Bc*Hc*Tc*DHc];     // [b,h,t,d]
__device__ float g_k[Bc*Hc*Tc*DHc];
__device__ float g_v[Bc*Hc*Tc*DHc];
__device__ float g_att[Bc*Tc*Cc];       // normalized retention out, [b,t,h*dh]

// ---------------------------------------------------------------------------
// NT-GEMM: out[m,n] = sum_k A[m,k] * W[n,k]   (M=4096, N=1024, K=1024)
// dest 0/1/2 -> write q/k/v in [b,h,t,d] layout; dest 3 -> plain [m,n] to outp,
// reading A from g_att.
// ---------------------------------------------------------------------------
__global__ void __launch_bounds__(256) gemm_nt_kernel(
    const float* __restrict__ A_in, const float* __restrict__ W,
    float* __restrict__ outp, int dest)
{
    __shared__ float As[16*128];
    __shared__ float Bs[16*128];
    const int K = 1024;

    const float* A = (dest == 3) ? g_att : A_in;

    int tid = threadIdx.x;
    int ty = tid >> 4, tx = tid & 15;
    int m0 = blockIdx.y * 128;
    int n0 = blockIdx.x * 128;

    float acc[8][8];
    #pragma unroll
    for (int i = 0; i < 8; i++)
        #pragma unroll
        for (int j = 0; j < 8; j++) acc[i][j] = 0.f;

    for (int k0 = 0; k0 < K; k0 += 16) {
        #pragma unroll
        for (int u = 0; u < 2; u++) {
            int fid = tid + u*256;          // 0..511
            int row = fid >> 2;             // 0..127
            int c   = (fid & 3) * 4;        // 0,4,8,12
            float4 va = *(const float4*)(A + (size_t)(m0+row)*K + k0 + c);
            As[(c+0)*128+row] = va.x; As[(c+1)*128+row] = va.y;
            As[(c+2)*128+row] = va.z; As[(c+3)*128+row] = va.w;
            float4 vb = *(const float4*)(W + (size_t)(n0+row)*K + k0 + c);
            Bs[(c+0)*128+row] = vb.x; Bs[(c+1)*128+row] = vb.y;
            Bs[(c+2)*128+row] = vb.z; Bs[(c+3)*128+row] = vb.w;
        }
        __syncthreads();
        #pragma unroll
        for (int k = 0; k < 16; k++) {
            float a[8], b[8];
            *(float4*)(a)   = *(const float4*)(As + k*128 + ty*4);
            *(float4*)(a+4) = *(const float4*)(As + k*128 + 64 + ty*4);
            *(float4*)(b)   = *(const float4*)(Bs + k*128 + tx*4);
            *(float4*)(b+4) = *(const float4*)(Bs + k*128 + 64 + tx*4);
            #pragma unroll
            for (int i = 0; i < 8; i++)
                #pragma unroll
                for (int j = 0; j < 8; j++)
                    acc[i][j] += a[i]*b[j];
        }
        __syncthreads();
    }

    float* out = (dest == 0) ? g_q : (dest == 1) ? g_k : (dest == 2) ? g_v : outp;

    #pragma unroll
    for (int i = 0; i < 8; i++) {
        int m = m0 + ((i < 4) ? (ty*4 + i) : (64 + ty*4 + i - 4));
        #pragma unroll
        for (int jh = 0; jh < 2; jh++) {
            int n = n0 + jh*64 + tx*4;
            float4 v = make_float4(acc[i][jh*4+0], acc[i][jh*4+1],
                                   acc[i][jh*4+2], acc[i][jh*4+3]);
            size_t oidx;
            if (dest < 3) {
                int bb = m >> 11, t = m & 2047, h = n >> 6, d = n & 63;
                oidx = (((size_t)bb*Hc + h)*Tc + t)*DHc + d;
            } else {
                oidx = (size_t)m*Cc + n;
            }
            *(float4*)(out + oidx) = v;
        }
    }
}

// ---------------------------------------------------------------------------
// RoPE in place on g_q / g_k. One thread per (bh, t, j) pair; pair (j, j+32).
// ---------------------------------------------------------------------------
__global__ void __launch_bounds__(256) rope_kernel()
{
    int gid = blockIdx.x * 256 + threadIdx.x;   // 0 .. 2,097,151
    int j  = gid & 31;
    int t  = (gid >> 5) & 2047;
    int bh = gid >> 16;

    float* arr = (blockIdx.y == 0) ? g_q : g_k;
    size_t base = ((size_t)bh * Tc + t) * DHc;

    // inv_freq = 10000^(-2j/64) = 2^(-j * log2(10000)/32)
    float inv = exp2f(-(float)j * (13.287712379549449f / 32.0f));
    float ang = (float)t * inv;
    float sn, cs;
    sincosf(ang, &sn, &cs);

    float x1 = arr[base + j];
    float x2 = arr[base + j + 32];
    arr[base + j]      = x1*cs - x2*sn;
    arr[base + j + 32] = x2*cs + x1*sn;
}

// ---------------------------------------------------------------------------
// Retention + fused GroupNorm.
// Block = one (bh, 64-row t-tile). Loops over causal s-tiles of 64.
//   smem: Qs [d][t] (64x68), KV (K as [d][s], then V as [s][d]) (64x68),
//         Ss = S^T [s][t] (64x68), reused as O [t][d] for the norm epilogue.
// Decay folded as 0.125 * gamma^(t0-s0) * gamma^tl * gamma^(-sl).
// ---------------------------------------------------------------------------
#define ATT_SMEM (3 * 64 * 68 * 4)

__global__ void __launch_bounds__(256) retention_kernel(
    const float* __restrict__ gnw, const float* __restrict__ gnb)
{
    extern __shared__ float sm[];
    float* Qs = sm;               // [d][t], stride 68
    float* KV = sm + 64*68;       // K: [d][s]; V: [s][d], stride 68
    float* Ss = sm + 2*64*68;     // S^T: [s][t]; later O: [t][d], stride 68

    int tid = threadIdx.x;
    int ty = tid >> 4, tx = tid & 15;
    int tt = blockIdx.x;          // t-tile
    int bh = blockIdx.y;
    int h  = bh & (Hc-1);
    int t0 = tt * 64;

    const float* qb = g_q + (size_t)bh * Tc * DHc;
    const float* kb = g_k + (size_t)bh * Tc * DHc;
    const float* vb = g_v + (size_t)bh * Tc * DHc;

    float gamma = 1.0f - exp2f(-5.0f - (float)h);
    float lg = log2f(gamma);      // negative, tiny magnitude

    // Load Q tile transposed: Qs[d][t]
    #pragma unroll
    for (int u = 0; u < 16; u++) {
        int idx = tid + u*256;
        int r = idx >> 6, d = idx & 63;
        Qs[d*68 + r] = qb[(size_t)(t0 + r)*DHc + d];
    }

    float rowf[4], colf[4];
    #pragma unroll
    for (int i = 0; i < 4; i++) rowf[i] = exp2f((float)(ty*4 + i) * lg);
    #pragma unroll
    for (int j = 0; j < 4; j++) colf[j] = exp2f(-(float)(tx*4 + j) * lg);

    float o[4][4];
    #pragma unroll
    for (int i = 0; i < 4; i++)
        #pragma unroll
        for (int j = 0; j < 4; j++) o[i][j] = 0.f;

    __syncthreads();

    for (int st = 0; st <= tt; st++) {
        int s0 = st * 64;

        // Load K tile transposed: KV[d][s]
        #pragma unroll
        for (int u = 0; u < 16; u++) {
            int idx = tid + u*256;
            int r = idx >> 6, d = idx & 63;
            KV[d*68 + r] = kb[(size_t)(s0 + r)*DHc + d];
        }
        __syncthreads();

        // S = Q K^T  (inner dim d = 64)
        float s_acc[4][4];
        #pragma unroll
        for (int i = 0; i < 4; i++)
            #pragma unroll
            for (int j = 0; j < 4; j++) s_acc[i][j] = 0.f;

        #pragma unroll 16
        for (int d = 0; d < 64; d++) {
            float4 qf = *(const float4*)(Qs + d*68 + ty*4);
            float4 kf = *(const float4*)(KV + d*68 + tx*4);
            float qa[4] = {qf.x, qf.y, qf.z, qf.w};
            float ka[4] = {kf.x, kf.y, kf.z, kf.w};
            #pragma unroll
            for (int i = 0; i < 4; i++)
                #pragma unroll
                for (int j = 0; j < 4; j++)
                    s_acc[i][j] += qa[i]*ka[j];
        }

        // Decay * scale (+ causal mask on diagonal tile)
        float base = exp2f((float)(t0 - s0) * lg) * 0.125f;
        if (st == tt) {
            #pragma unroll
            for (int i = 0; i < 4; i++)
                #pragma unroll
                for (int j = 0; j < 4; j++) {
                    int diff = (ty*4 + i) - (tx*4 + j);
                    s_acc[i][j] = (diff < 0) ? 0.f
                                : s_acc[i][j] * base * rowf[i] * colf[j];
                }
        } else {
            #pragma unroll
            for (int i = 0; i < 4; i++)
                #pragma unroll
                for (int j = 0; j < 4; j++)
                    s_acc[i][j] *= base * rowf[i] * colf[j];
        }
        __syncthreads();   // all K reads done before V overwrites KV

        // Store S^T: Ss[s][t]
        #pragma unroll
        for (int j = 0; j < 4; j++) {
            float4 v4 = make_float4(s_acc[0][j], s_acc[1][j], s_acc[2][j], s_acc[3][j]);
            *(float4*)(Ss + (tx*4 + j)*68 + ty*4) = v4;
        }
        // Load V tile natural: KV[s][d]
        #pragma unroll
        for (int u = 0; u < 4; u++) {
            int fid = tid + u*256;            // 0..1023 float4s
            int r = fid >> 4, c = (fid & 15) * 4;
            *(float4*)(KV + r*68 + c) = *(const float4*)(vb + (size_t)(s0 + r)*DHc + c);
        }
        __syncthreads();

        // O += S V  (inner dim s = 64)
        #pragma unroll 16
        for (int s = 0; s < 64; s++) {
            float4 sf = *(const float4*)(Ss + s*68 + ty*4);
            float4 vf = *(const float4*)(KV + s*68 + tx*4);
            float sa[4] = {sf.x, sf.y, sf.z, sf.w};
            float va[4] = {vf.x, vf.y, vf.z, vf.w};
            #pragma unroll
            for (int i = 0; i < 4; i++)
                #pragma unroll
                for (int j = 0; j < 4; j++)
                    o[i][j] += sa[i]*va[j];
        }
        __syncthreads();
    }

    // Stage O into smem as [t][d] (reuse Ss)
    #pragma unroll
    for (int i = 0; i < 4; i++) {
        float4 v4 = make_float4(o[i][0], o[i][1], o[i][2], o[i][3]);
        *(float4*)(Ss + (ty*4 + i)*68 + tx*4) = v4;
    }
    __syncthreads();

    // GroupNorm per t-row over DH=64, write to g_att[b][t][h*64+d]
    if (tid < 64) {
        int r = tid;
        const float* row = Ss + r*68;
        float mu = 0.f;
        #pragma unroll
        for (int c = 0; c < 64; c++) mu += row[c];
        mu *= (1.0f/64.0f);
        float var = 0.f;
        #pragma unroll
        for (int c = 0; c < 64; c++) { float d = row[c] - mu; var += d*d; }
        var *= (1.0f/64.0f);
        float rs = rsqrtf(var + 1e-5f);

        int b = bh >> 4;
        size_t obase = ((size_t)b*Tc + t0 + r) * Cc + h*64;
        #pragma unroll
        for (int c = 0; c < 64; c++)
            g_att[obase + c] = (row[c] - mu) * rs * gnw[h*64 + c] + gnb[h*64 + c];
    }
}

// ---------------------------------------------------------------------------
extern "C" void kernel_launch(void* const* d_in, const int* in_sizes, int n_in,
                              void* d_out, int out_size)
{
    const float* x   = (const float*)d_in[0];
    const float* Wq  = (const float*)d_in[1];
    const float* Wk  = (const float*)d_in[2];
    const float* Wv  = (const float*)d_in[3];
    const float* Wo  = (const float*)d_in[4];
    const float* gnw = (const float*)d_in[5];
    const float* gnb = (const float*)d_in[6];
    float* out = (float*)d_out;

    // >48KB dynamic smem opt-in for the retention kernel (idempotent host call)
    cudaFuncSetAttribute(retention_kernel,
                         cudaFuncAttributeMaxDynamicSharedMemorySize, ATT_SMEM);

    dim3 gg(8, 32);   // N/128 x M/128
    gemm_nt_kernel<<<gg, 256>>>(x, Wq, nullptr, 0);
    gemm_nt_kernel<<<gg, 256>>>(x, Wk, nullptr, 1);
    gemm_nt_kernel<<<gg, 256>>>(x, Wv, nullptr, 2);

    rope_kernel<<<dim3(8192, 2), 256>>>();

    retention_kernel<<<dim3(Tc/64, Bc*Hc), 256, ATT_SMEM>>>(gnw, gnb);

    gemm_nt_kernel<<<gg, 256>>>(nullptr, Wo, out, 3);
}

// round 5
// speedup vs baseline: 1.0052x; 1.0052x over previous
#include <cuda_runtime.h>
#include <cstdint>

// Problem constants
#define Bc  2
#define Tc  2048
#define Cc  1024
#define Hc  16
#define DHc 64

// Scratch (device globals: no allocations allowed)
__device__ float g_q[Bc*Hc*Tc*DHc];     // [b,h,t,d]
__device__ float g_k[Bc*Hc*Tc*DHc];
__device__ float g_v[Bc*Hc*Tc*DHc];
__device__ float g_att[Bc*Tc*Cc];       // normalized retention out, [b,t,h*dh]

// ---------------------------------------------------------------------------
// NT-GEMM: out[m,n] = sum_k A[m,k] * W[n,k]   (M=4096, N=1024, K=1024)
// dest 0/1/2 -> write q/k/v in [b,h,t,d] layout; dest 3 -> plain [m,n] to outp,
// reading A from g_att.
// ---------------------------------------------------------------------------
__global__ void __launch_bounds__(256) gemm_nt_kernel(
    const float* __restrict__ A_in, const float* __restrict__ W,
    float* __restrict__ outp, int dest)
{
    __shared__ float As[16*128];
    __shared__ float Bs[16*128];
    const int K = 1024;

    const float* A = (dest == 3) ? g_att : A_in;

    int tid = threadIdx.x;
    int ty = tid >> 4, tx = tid & 15;
    int m0 = blockIdx.y * 128;
    int n0 = blockIdx.x * 128;

    float acc[8][8];
    #pragma unroll
    for (int i = 0; i < 8; i++)
        #pragma unroll
        for (int j = 0; j < 8; j++) acc[i][j] = 0.f;

    for (int k0 = 0; k0 < K; k0 += 16) {
        #pragma unroll
        for (int u = 0; u < 2; u++) {
            int fid = tid + u*256;          // 0..511
            int row = fid >> 2;             // 0..127
            int c   = (fid & 3) * 4;        // 0,4,8,12
            float4 va = *(const float4*)(A + (size_t)(m0+row)*K + k0 + c);
            As[(c+0)*128+row] = va.x; As[(c+1)*128+row] = va.y;
            As[(c+2)*128+row] = va.z; As[(c+3)*128+row] = va.w;
            float4 vb = *(const float4*)(W + (size_t)(n0+row)*K + k0 + c);
            Bs[(c+0)*128+row] = vb.x; Bs[(c+1)*128+row] = vb.y;
            Bs[(c+2)*128+row] = vb.z; Bs[(c+3)*128+row] = vb.w;
        }
        __syncthreads();
        #pragma unroll
        for (int k = 0; k < 16; k++) {
            float a[8], b[8];
            *(float4*)(a)   = *(const float4*)(As + k*128 + ty*4);
            *(float4*)(a+4) = *(const float4*)(As + k*128 + 64 + ty*4);
            *(float4*)(b)   = *(const float4*)(Bs + k*128 + tx*4);
            *(float4*)(b+4) = *(const float4*)(Bs + k*128 + 64 + tx*4);
            #pragma unroll
            for (int i = 0; i < 8; i++)
                #pragma unroll
                for (int j = 0; j < 8; j++)
                    acc[i][j] += a[i]*b[j];
        }
        __syncthreads();
    }

    float* out = (dest == 0) ? g_q : (dest == 1) ? g_k : (dest == 2) ? g_v : outp;

    #pragma unroll
    for (int i = 0; i < 8; i++) {
        int m = m0 + ((i < 4) ? (ty*4 + i) : (64 + ty*4 + i - 4));
        #pragma unroll
        for (int jh = 0; jh < 2; jh++) {
            int n = n0 + jh*64 + tx*4;
            float4 v = make_float4(acc[i][jh*4+0], acc[i][jh*4+1],
                                   acc[i][jh*4+2], acc[i][jh*4+3]);
            size_t oidx;
            if (dest < 3) {
                int bb = m >> 11, t = m & 2047, h = n >> 6, d = n & 63;
                oidx = (((size_t)bb*Hc + h)*Tc + t)*DHc + d;
            } else {
                oidx = (size_t)m*Cc + n;
            }
            *(float4*)(out + oidx) = v;
        }
    }
}

// ---------------------------------------------------------------------------
// RoPE in place on g_q / g_k. One thread per (bh, t, j) pair; pair (j, j+32).
// ---------------------------------------------------------------------------
__global__ void __launch_bounds__(256) rope_kernel()
{
    int gid = blockIdx.x * 256 + threadIdx.x;   // 0 .. 2,097,151
    int j  = gid & 31;
    int t  = (gid >> 5) & 2047;
    int bh = gid >> 16;

    float* arr = (blockIdx.y == 0) ? g_q : g_k;
    size_t base = ((size_t)bh * Tc + t) * DHc;

    // inv_freq = 10000^(-2j/64) = 2^(-j * log2(10000)/32)
    float inv = exp2f(-(float)j * (13.287712379549449f / 32.0f));
    float ang = (float)t * inv;
    float sn, cs;
    sincosf(ang, &sn, &cs);

    float x1 = arr[base + j];
    float x2 = arr[base + j + 32];
    arr[base + j]      = x1*cs - x2*sn;
    arr[base + j + 32] = x2*cs + x1*sn;
}

// ---------------------------------------------------------------------------
// Retention + fused GroupNorm.
// Block = one (bh, 64-row t-tile). Loops over causal s-tiles of 64.
//   smem: Qs [d][t] (64x68), KV (K as [d][s], then V as [s][d]) (64x68),
//         Ss = S^T [s][t] (64x68), reused as O [t][d] for the norm epilogue.
// Decay folded as 0.125 * gamma^(t0-s0) * gamma^tl * gamma^(-sl).
// ---------------------------------------------------------------------------
#define ATT_SMEM (3 * 64 * 68 * 4)

__global__ void __launch_bounds__(256) retention_kernel(
    const float* __restrict__ gnw, const float* __restrict__ gnb)
{
    extern __shared__ float sm[];
    float* Qs = sm;               // [d][t], stride 68
    float* KV = sm + 64*68;       // K: [d][s]; V: [s][d], stride 68
    float* Ss = sm + 2*64*68;     // S^T: [s][t]; later O: [t][d], stride 68

    int tid = threadIdx.x;
    int ty = tid >> 4, tx = tid & 15;
    int tt = blockIdx.x;          // t-tile
    int bh = blockIdx.y;
    int h  = bh & (Hc-1);
    int t0 = tt * 64;

    const float* qb = g_q + (size_t)bh * Tc * DHc;
    const float* kb = g_k + (size_t)bh * Tc * DHc;
    const float* vb = g_v + (size_t)bh * Tc * DHc;

    float gamma = 1.0f - exp2f(-5.0f - (float)h);
    float lg = log2f(gamma);      // negative, tiny magnitude

    // Load Q tile transposed: Qs[d][t]
    #pragma unroll
    for (int u = 0; u < 16; u++) {
        int idx = tid + u*256;
        int r = idx >> 6, d = idx & 63;
        Qs[d*68 + r] = qb[(size_t)(t0 + r)*DHc + d];
    }

    float rowf[4], colf[4];
    #pragma unroll
    for (int i = 0; i < 4; i++) rowf[i] = exp2f((float)(ty*4 + i) * lg);
    #pragma unroll
    for (int j = 0; j < 4; j++) colf[j] = exp2f(-(float)(tx*4 + j) * lg);

    float o[4][4];
    #pragma unroll
    for (int i = 0; i < 4; i++)
        #pragma unroll
        for (int j = 0; j < 4; j++) o[i][j] = 0.f;

    __syncthreads();

    for (int st = 0; st <= tt; st++) {
        int s0 = st * 64;

        // Load K tile transposed: KV[d][s]
        #pragma unroll
        for (int u = 0; u < 16; u++) {
            int idx = tid + u*256;
            int r = idx >> 6, d = idx & 63;
            KV[d*68 + r] = kb[(size_t)(s0 + r)*DHc + d];
        }
        __syncthreads();

        // S = Q K^T  (inner dim d = 64)
        float s_acc[4][4];
        #pragma unroll
        for (int i = 0; i < 4; i++)
            #pragma unroll
            for (int j = 0; j < 4; j++) s_acc[i][j] = 0.f;

        #pragma unroll 16
        for (int d = 0; d < 64; d++) {
            float4 qf = *(const float4*)(Qs + d*68 + ty*4);
            float4 kf = *(const float4*)(KV + d*68 + tx*4);
            float qa[4] = {qf.x, qf.y, qf.z, qf.w};
            float ka[4] = {kf.x, kf.y, kf.z, kf.w};
            #pragma unroll
            for (int i = 0; i < 4; i++)
                #pragma unroll
                for (int j = 0; j < 4; j++)
                    s_acc[i][j] += qa[i]*ka[j];
        }

        // Decay * scale (+ causal mask on diagonal tile)
        float base = exp2f((float)(t0 - s0) * lg) * 0.125f;
        if (st == tt) {
            #pragma unroll
            for (int i = 0; i < 4; i++)
                #pragma unroll
                for (int j = 0; j < 4; j++) {
                    int diff = (ty*4 + i) - (tx*4 + j);
                    s_acc[i][j] = (diff < 0) ? 0.f
                                : s_acc[i][j] * base * rowf[i] * colf[j];
                }
        } else {
            #pragma unroll
            for (int i = 0; i < 4; i++)
                #pragma unroll
                for (int j = 0; j < 4; j++)
                    s_acc[i][j] *= base * rowf[i] * colf[j];
        }
        __syncthreads();   // all K reads done before V overwrites KV

        // Store S^T: Ss[s][t]
        #pragma unroll
        for (int j = 0; j < 4; j++) {
            float4 v4 = make_float4(s_acc[0][j], s_acc[1][j], s_acc[2][j], s_acc[3][j]);
            *(float4*)(Ss + (tx*4 + j)*68 + ty*4) = v4;
        }
        // Load V tile natural: KV[s][d]
        #pragma unroll
        for (int u = 0; u < 4; u++) {
            int fid = tid + u*256;            // 0..1023 float4s
            int r = fid >> 4, c = (fid & 15) * 4;
            *(float4*)(KV + r*68 + c) = *(const float4*)(vb + (size_t)(s0 + r)*DHc + c);
        }
        __syncthreads();

        // O += S V  (inner dim s = 64)
        #pragma unroll 16
        for (int s = 0; s < 64; s++) {
            float4 sf = *(const float4*)(Ss + s*68 + ty*4);
            float4 vf = *(const float4*)(KV + s*68 + tx*4);
            float sa[4] = {sf.x, sf.y, sf.z, sf.w};
            float va[4] = {vf.x, vf.y, vf.z, vf.w};
            #pragma unroll
            for (int i = 0; i < 4; i++)
                #pragma unroll
                for (int j = 0; j < 4; j++)
                    o[i][j] += sa[i]*va[j];
        }
        __syncthreads();
    }

    // Stage O into smem as [t][d] (reuse Ss)
    #pragma unroll
    for (int i = 0; i < 4; i++) {
        float4 v4 = make_float4(o[i][0], o[i][1], o[i][2], o[i][3]);
        *(float4*)(Ss + (ty*4 + i)*68 + tx*4) = v4;
    }
    __syncthreads();

    // GroupNorm per t-row over DH=64, write to g_att[b][t][h*64+d]
    if (tid < 64) {
        int r = tid;
        const float* row = Ss + r*68;
        float mu = 0.f;
        #pragma unroll
        for (int c = 0; c < 64; c++) mu += row[c];
        mu *= (1.0f/64.0f);
        float var = 0.f;
        #pragma unroll
        for (int c = 0; c < 64; c++) { float d = row[c] - mu; var += d*d; }
        var *= (1.0f/64.0f);
        float rs = rsqrtf(var + 1e-5f);

        int b = bh >> 4;
        size_t obase = ((size_t)b*Tc + t0 + r) * Cc + h*64;
        #pragma unroll
        for (int c = 0; c < 64; c++)
            g_att[obase + c] = (row[c] - mu) * rs * gnw[h*64 + c] + gnb[h*64 + c];
    }
}

// ---------------------------------------------------------------------------
extern "C" void kernel_launch(void* const* d_in, const int* in_sizes, int n_in,
                              void* d_out, int out_size)
{
    const float* x   = (const float*)d_in[0];
    const float* Wq  = (const float*)d_in[1];
    const float* Wk  = (const float*)d_in[2];
    const float* Wv  = (const float*)d_in[3];
    const float* Wo  = (const float*)d_in[4];
    const float* gnw = (const float*)d_in[5];
    const float* gnb = (const float*)d_in[6];
    float* out = (float*)d_out;

    // >48KB dynamic smem opt-in for the retention kernel (idempotent host call)
    cudaFuncSetAttribute(retention_kernel,
                         cudaFuncAttributeMaxDynamicSharedMemorySize, ATT_SMEM);

    dim3 gg(8, 32);   // N/128 x M/128
    gemm_nt_kernel<<<gg, 256>>>(x, Wq, nullptr, 0);
    gemm_nt_kernel<<<gg, 256>>>(x, Wk, nullptr, 1);
    gemm_nt_kernel<<<gg, 256>>>(x, Wv, nullptr, 2);

    rope_kernel<<<dim3(8192, 2), 256>>>();

    retention_kernel<<<dim3(Tc/64, Bc*Hc), 256, ATT_SMEM>>>(gnw, gnb);

    gemm_nt_kernel<<<gg, 256>>>(nullptr, Wo, out, 3);
}

// round 6
// speedup vs baseline: 1.0148x; 1.0096x over previous
#include <cuda_runtime.h>
#include <cstdint>

// Problem constants
#define Bc  2
#define Tc  2048
#define Cc  1024
#define Hc  16
#define DHc 64

// Scratch (device globals: no allocations allowed)
__device__ float g_q[Bc*Hc*Tc*DHc];     // [b,h,t,d]
__device__ float g_k[Bc*Hc*Tc*DHc];
__device__ float g_v[Bc*Hc*Tc*DHc];
__device__ float g_att[Bc*Tc*Cc];       // normalized retention out, [b,t,h*dh]

// ---------------------------------------------------------------------------
// NT-GEMM: out[m,n] = sum_k A[m,k] * W[n,k]   (M=4096, N=1024, K=1024)
// dest 0/1/2 -> write q/k/v in [b,h,t,d] layout; dest 3 -> plain [m,n] to outp,
// reading A from g_att.
// ---------------------------------------------------------------------------
__global__ void __launch_bounds__(256) gemm_nt_kernel(
    const float* __restrict__ A_in, const float* __restrict__ W,
    float* __restrict__ outp, int dest)
{
    __shared__ float As[16*128];
    __shared__ float Bs[16*128];
    const int K = 1024;

    const float* A = (dest == 3) ? g_att : A_in;

    int tid = threadIdx.x;
    int ty = tid >> 4, tx = tid & 15;
    int m0 = blockIdx.y * 128;
    int n0 = blockIdx.x * 128;

    float acc[8][8];
    #pragma unroll
    for (int i = 0; i < 8; i++)
        #pragma unroll
        for (int j = 0; j < 8; j++) acc[i][j] = 0.f;

    for (int k0 = 0; k0 < K; k0 += 16) {
        #pragma unroll
        for (int u = 0; u < 2; u++) {
            int fid = tid + u*256;          // 0..511
            int row = fid >> 2;             // 0..127
            int c   = (fid & 3) * 4;        // 0,4,8,12
            float4 va = *(const float4*)(A + (size_t)(m0+row)*K + k0 + c);
            As[(c+0)*128+row] = va.x; As[(c+1)*128+row] = va.y;
            As[(c+2)*128+row] = va.z; As[(c+3)*128+row] = va.w;
            float4 vb = *(const float4*)(W + (size_t)(n0+row)*K + k0 + c);
            Bs[(c+0)*128+row] = vb.x; Bs[(c+1)*128+row] = vb.y;
            Bs[(c+2)*128+row] = vb.z; Bs[(c+3)*128+row] = vb.w;
        }
        __syncthreads();
        #pragma unroll
        for (int k = 0; k < 16; k++) {
            float a[8], b[8];
            *(float4*)(a)   = *(const float4*)(As + k*128 + ty*4);
            *(float4*)(a+4) = *(const float4*)(As + k*128 + 64 + ty*4);
            *(float4*)(b)   = *(const float4*)(Bs + k*128 + tx*4);
            *(float4*)(b+4) = *(const float4*)(Bs + k*128 + 64 + tx*4);
            #pragma unroll
            for (int i = 0; i < 8; i++)
                #pragma unroll
                for (int j = 0; j < 8; j++)
                    acc[i][j] += a[i]*b[j];
        }
        __syncthreads();
    }

    float* out = (dest == 0) ? g_q : (dest == 1) ? g_k : (dest == 2) ? g_v : outp;

    #pragma unroll
    for (int i = 0; i < 8; i++) {
        int m = m0 + ((i < 4) ? (ty*4 + i) : (64 + ty*4 + i - 4));
        #pragma unroll
        for (int jh = 0; jh < 2; jh++) {
            int n = n0 + jh*64 + tx*4;
            float4 v = make_float4(acc[i][jh*4+0], acc[i][jh*4+1],
                                   acc[i][jh*4+2], acc[i][jh*4+3]);
            size_t oidx;
            if (dest < 3) {
                int bb = m >> 11, t = m & 2047, h = n >> 6, d = n & 63;
                oidx = (((size_t)bb*Hc + h)*Tc + t)*DHc + d;
            } else {
                oidx = (size_t)m*Cc + n;
            }
            *(float4*)(out + oidx) = v;
        }
    }
}

// ---------------------------------------------------------------------------
// RoPE in place on g_q / g_k. One thread per (bh, t, j) pair; pair (j, j+32).
// ---------------------------------------------------------------------------
__global__ void __launch_bounds__(256) rope_kernel()
{
    int gid = blockIdx.x * 256 + threadIdx.x;   // 0 .. 2,097,151
    int j  = gid & 31;
    int t  = (gid >> 5) & 2047;
    int bh = gid >> 16;

    float* arr = (blockIdx.y == 0) ? g_q : g_k;
    size_t base = ((size_t)bh * Tc + t) * DHc;

    // inv_freq = 10000^(-2j/64) = 2^(-j * log2(10000)/32)
    float inv = exp2f(-(float)j * (13.287712379549449f / 32.0f));
    float ang = (float)t * inv;
    float sn, cs;
    sincosf(ang, &sn, &cs);

    float x1 = arr[base + j];
    float x2 = arr[base + j + 32];
    arr[base + j]      = x1*cs - x2*sn;
    arr[base + j + 32] = x2*cs + x1*sn;
}

// ---------------------------------------------------------------------------
// Retention + fused GroupNorm.
// Block = one (bh, 64-row t-tile). Loops over causal s-tiles of 64.
//   smem: Qs [d][t] (64x68), KV (K as [d][s], then V as [s][d]) (64x68),
//         Ss = S^T [s][t] (64x68), reused as O [t][d] for the norm epilogue.
// Decay folded as 0.125 * gamma^(t0-s0) * gamma^tl * gamma^(-sl).
// ---------------------------------------------------------------------------
#define ATT_SMEM (3 * 64 * 68 * 4)

__global__ void __launch_bounds__(256) retention_kernel(
    const float* __restrict__ gnw, const float* __restrict__ gnb)
{
    extern __shared__ float sm[];
    float* Qs = sm;               // [d][t], stride 68
    float* KV = sm + 64*68;       // K: [d][s]; V: [s][d], stride 68
    float* Ss = sm + 2*64*68;     // S^T: [s][t]; later O: [t][d], stride 68

    int tid = threadIdx.x;
    int ty = tid >> 4, tx = tid & 15;
    int tt = blockIdx.x;          // t-tile
    int bh = blockIdx.y;
    int h  = bh & (Hc-1);
    int t0 = tt * 64;

    const float* qb = g_q + (size_t)bh * Tc * DHc;
    const float* kb = g_k + (size_t)bh * Tc * DHc;
    const float* vb = g_v + (size_t)bh * Tc * DHc;

    float gamma = 1.0f - exp2f(-5.0f - (float)h);
    float lg = log2f(gamma);      // negative, tiny magnitude

    // Load Q tile transposed: Qs[d][t]
    #pragma unroll
    for (int u = 0; u < 16; u++) {
        int idx = tid + u*256;
        int r = idx >> 6, d = idx & 63;
        Qs[d*68 + r] = qb[(size_t)(t0 + r)*DHc + d];
    }

    float rowf[4], colf[4];
    #pragma unroll
    for (int i = 0; i < 4; i++) rowf[i] = exp2f((float)(ty*4 + i) * lg);
    #pragma unroll
    for (int j = 0; j < 4; j++) colf[j] = exp2f(-(float)(tx*4 + j) * lg);

    float o[4][4];
    #pragma unroll
    for (int i = 0; i < 4; i++)
        #pragma unroll
        for (int j = 0; j < 4; j++) o[i][j] = 0.f;

    __syncthreads();

    for (int st = 0; st <= tt; st++) {
        int s0 = st * 64;

        // Load K tile transposed: KV[d][s]
        #pragma unroll
        for (int u = 0; u < 16; u++) {
            int idx = tid + u*256;
            int r = idx >> 6, d = idx & 63;
            KV[d*68 + r] = kb[(size_t)(s0 + r)*DHc + d];
        }
        __syncthreads();

        // S = Q K^T  (inner dim d = 64)
        float s_acc[4][4];
        #pragma unroll
        for (int i = 0; i < 4; i++)
            #pragma unroll
            for (int j = 0; j < 4; j++) s_acc[i][j] = 0.f;

        #pragma unroll 16
        for (int d = 0; d < 64; d++) {
            float4 qf = *(const float4*)(Qs + d*68 + ty*4);
            float4 kf = *(const float4*)(KV + d*68 + tx*4);
            float qa[4] = {qf.x, qf.y, qf.z, qf.w};
            float ka[4] = {kf.x, kf.y, kf.z, kf.w};
            #pragma unroll
            for (int i = 0; i < 4; i++)
                #pragma unroll
                for (int j = 0; j < 4; j++)
                    s_acc[i][j] += qa[i]*ka[j];
        }

        // Decay * scale (+ causal mask on diagonal tile)
        float base = exp2f((float)(t0 - s0) * lg) * 0.125f;
        if (st == tt) {
            #pragma unroll
            for (int i = 0; i < 4; i++)
                #pragma unroll
                for (int j = 0; j < 4; j++) {
                    int diff = (ty*4 + i) - (tx*4 + j);
                    s_acc[i][j] = (diff < 0) ? 0.f
                                : s_acc[i][j] * base * rowf[i] * colf[j];
                }
        } else {
            #pragma unroll
            for (int i = 0; i < 4; i++)
                #pragma unroll
                for (int j = 0; j < 4; j++)
                    s_acc[i][j] *= base * rowf[i] * colf[j];
        }
        __syncthreads();   // all K reads done before V overwrites KV

        // Store S^T: Ss[s][t]
        #pragma unroll
        for (int j = 0; j < 4; j++) {
            float4 v4 = make_float4(s_acc[0][j], s_acc[1][j], s_acc[2][j], s_acc[3][j]);
            *(float4*)(Ss + (tx*4 + j)*68 + ty*4) = v4;
        }
        // Load V tile natural: KV[s][d]
        #pragma unroll
        for (int u = 0; u < 4; u++) {
            int fid = tid + u*256;            // 0..1023 float4s
            int r = fid >> 4, c = (fid & 15) * 4;
            *(float4*)(KV + r*68 + c) = *(const float4*)(vb + (size_t)(s0 + r)*DHc + c);
        }
        __syncthreads();

        // O += S V  (inner dim s = 64)
        #pragma unroll 16
        for (int s = 0; s < 64; s++) {
            float4 sf = *(const float4*)(Ss + s*68 + ty*4);
            float4 vf = *(const float4*)(KV + s*68 + tx*4);
            float sa[4] = {sf.x, sf.y, sf.z, sf.w};
            float va[4] = {vf.x, vf.y, vf.z, vf.w};
            #pragma unroll
            for (int i = 0; i < 4; i++)
                #pragma unroll
                for (int j = 0; j < 4; j++)
                    o[i][j] += sa[i]*va[j];
        }
        __syncthreads();
    }

    // Stage O into smem as [t][d] (reuse Ss)
    #pragma unroll
    for (int i = 0; i < 4; i++) {
        float4 v4 = make_float4(o[i][0], o[i][1], o[i][2], o[i][3]);
        *(float4*)(Ss + (ty*4 + i)*68 + tx*4) = v4;
    }
    __syncthreads();

    // GroupNorm per t-row over DH=64, write to g_att[b][t][h*64+d]
    if (tid < 64) {
        int r = tid;
        const float* row = Ss + r*68;
        float mu = 0.f;
        #pragma unroll
        for (int c = 0; c < 64; c++) mu += row[c];
        mu *= (1.0f/64.0f);
        float var = 0.f;
        #pragma unroll
        for (int c = 0; c < 64; c++) { float d = row[c] - mu; var += d*d; }
        var *= (1.0f/64.0f);
        float rs = rsqrtf(var + 1e-5f);

        int b = bh >> 4;
        size_t obase = ((size_t)b*Tc + t0 + r) * Cc + h*64;
        #pragma unroll
        for (int c = 0; c < 64; c++)
            g_att[obase + c] = (row[c] - mu) * rs * gnw[h*64 + c] + gnb[h*64 + c];
    }
}

// ---------------------------------------------------------------------------
extern "C" void kernel_launch(void* const* d_in, const int* in_sizes, int n_in,
                              void* d_out, int out_size)
{
    const float* x   = (const float*)d_in[0];
    const float* Wq  = (const float*)d_in[1];
    const float* Wk  = (const float*)d_in[2];
    const float* Wv  = (const float*)d_in[3];
    const float* Wo  = (const float*)d_in[4];
    const float* gnw = (const float*)d_in[5];
    const float* gnb = (const float*)d_in[6];
    float* out = (float*)d_out;

    // >48KB dynamic smem opt-in for the retention kernel (idempotent host call)
    cudaFuncSetAttribute(retention_kernel,
                         cudaFuncAttributeMaxDynamicSharedMemorySize, ATT_SMEM);

    dim3 gg(8, 32);   // N/128 x M/128
    gemm_nt_kernel<<<gg, 256>>>(x, Wq, nullptr, 0);
    gemm_nt_kernel<<<gg, 256>>>(x, Wk, nullptr, 1);
    gemm_nt_kernel<<<gg, 256>>>(x, Wv, nullptr, 2);

    rope_kernel<<<dim3(8192, 2), 256>>>();

    retention_kernel<<<dim3(Tc/64, Bc*Hc), 256, ATT_SMEM>>>(gnw, gnb);

    gemm_nt_kernel<<<gg, 256>>>(nullptr, Wo, out, 3);
}